// round 13
// baseline (speedup 1.0000x reference)
#include <cuda_runtime.h>
#include <cuda_fp16.h>
#include <cstdint>

#define Bsz 256
#define Lsz 500
#define Dsz 3
#define Csz 32
#define Isz 35
#define Hsz 512
#define Msz 5
#define Osz 15
#define Jsz 35
#define NC  50
#define LC  10
#define BH  (Bsz*Hsz)   /* 131072 */
#define BL  (Bsz*Lsz)   /* 128000 */
#define NSL 4           /* h slices */
#define HS  (Hsz/NSL)   /* 128 */
#define BT  128         /* b tile (k_all AND k_sums) */
#define NBT (Bsz/BT)    /* 2 */
#define XP  44          /* xs row stride (floats), k_sums */
#define NT  512         /* k_all threads */
#define NTS 1024        /* k_sums threads */
#define CP  136         /* c16 smem row stride (halfs) */
#define HP2 132         /* hs row stride (words) */

#define WCNT (Isz*HS)   /* 4480 */
#define XCNT (BT*XP)    /* 5632 */

// k_all smem byte layout (dynamic) -- R10 known-good
#define SM_VS0 0                         /* V tf32 bits [128][40] = 20480 B */
#define SM_VS1 (SM_VS0 + 20480)
#define SM_HS  (SM_VS1 + 20480)          /* relu(a) tf32 bits [128][132] = 67584 B */
#define SM_C0  (SM_HS + 67584)           /* c16 stage 128*136 halfs = 34816 B */
#define SM_C1  (SM_C0 + 34816)
#define SM_RED (SM_C1 + 34816)           /* K-half reduce buf [128][40] f32 = 20480 B */
#define SM_TOT (SM_RED + 20480)          /* 198656 B */

// ONE extern dynamic-smem symbol for the whole TU
extern __shared__ __align__(16) char dyn_smem[];

// Scratch
__device__ __align__(16) float  g_S[(size_t)NC * BH];
__device__ __align__(16) float  g_P[(size_t)NC * BH];
__device__ __align__(16) float  g_part[(size_t)NSL * BL * 40];
__device__ __align__(16) __half g_c16[(size_t)Lsz * BH];

using u64 = unsigned long long;

__device__ __forceinline__ u64 splat2(float x) {
    u64 r; unsigned u = __float_as_uint(x);
    asm("mov.b64 %0, {%1, %1};" : "=l"(r) : "r"(u));
    return r;
}
__device__ __forceinline__ u64 fma2(u64 a, u64 b, u64 c) {
    u64 d; asm("fma.rn.f32x2 %0, %1, %2, %3;" : "=l"(d) : "l"(a), "l"(b), "l"(c));
    return d;
}
__device__ __forceinline__ u64 add2(u64 a, u64 b) {
    u64 d; asm("add.rn.f32x2 %0, %1, %2;" : "=l"(d) : "l"(a), "l"(b));
    return d;
}
__device__ __forceinline__ void cp16(unsigned dst, const void* src) {
    asm volatile("cp.async.ca.shared.global [%0], [%1], 16;" :: "r"(dst), "l"(src));
}
__device__ __forceinline__ void cp4(unsigned dst, const void* src) {
    asm volatile("cp.async.ca.shared.global [%0], [%1], 4;" :: "r"(dst), "l"(src));
}
__device__ __forceinline__ void cp_commit() { asm volatile("cp.async.commit_group;"); }
__device__ __forceinline__ void cp_wait0()  { asm volatile("cp.async.wait_group 0;"); }
__device__ __forceinline__ unsigned f2tf32(float x) {
    unsigned r; asm("cvt.rna.tf32.f32 %0, %1;" : "=r"(r) : "f"(x)); return r;
}
// m16n8k8 tf32 HMMA (plain sm_80+ PTX; valid on the harness's sm_103 target)
__device__ __forceinline__ void mma_tf32(float d[4],
                                         unsigned a0, unsigned a1, unsigned a2, unsigned a3,
                                         unsigned b0, unsigned b1) {
    asm volatile(
        "mma.sync.aligned.m16n8k8.row.col.f32.tf32.tf32.f32 "
        "{%0,%1,%2,%3}, {%4,%5,%6,%7}, {%8,%9}, {%0,%1,%2,%3};"
        : "+f"(d[0]), "+f"(d[1]), "+f"(d[2]), "+f"(d[3])
        : "r"(a0), "r"(a1), "r"(a2), "r"(a3), "r"(b0), "r"(b1));
}

// ---------------------------------------------------------------------------
// k_sums v3: BT=128 (same traffic as the profiled 153us version) but 1024
// threads with a 2b x 8h thread tile -> ~60 regs -> 32 warps/SM.
// ---------------------------------------------------------------------------
__device__ __forceinline__ void stage_wx_async(unsigned ws_a, unsigned xs_a,
                                               const float* __restrict__ W,
                                               const float* __restrict__ inp,
                                               const float* __restrict__ zz,
                                               int l, int h0, int b0, int tid)
{
    const float4* wsrc = (const float4*)(W + (size_t)l * (Isz * Hsz)) + (h0 >> 2);
#pragma unroll
    for (int q = 0; q < 2; q++) {
        int idx = tid + NTS * q;
        if (idx < Isz * 32) {
            int row = idx >> 5, col = idx & 31;
            cp16(ws_a + (unsigned)(row * 32 + col) * 16, wsrc + row * 128 + col);
        }
    }
    // z part: 128 rows x 8 float4 = 1024 -> exactly one pass
    {
        int b = tid >> 3, qf = tid & 7;
        cp16(xs_a + (unsigned)(b * XP + 4 + qf * 4) * 4,
             zz + (size_t)(b0 + b) * (Lsz * Csz) + (size_t)l * Csz + qf * 4);
    }
    if (tid < BT * Dsz) {
        int b = tid / Dsz, i = tid % Dsz;
        cp4(xs_a + (unsigned)(b * XP + i) * 4,
            inp + (size_t)(b0 + b) * (Lsz * Dsz) + (size_t)l * Dsz + i);
    }
}

__device__ __forceinline__ void encode_step(u64 c2[2][4], const float* ws,
                                            const float* xs, int bg, int hg)
{
#pragma unroll
    for (int r = 0; r < 2; r++)
#pragma unroll
        for (int p = 0; p < 4; p++) c2[r][p] = 0ull;
#pragma unroll
    for (int i = 0; i < Isz; i++) {
        const int xc = (i < Dsz) ? i : i + 1;
        u64 xa[2], wv[4];
#pragma unroll
        for (int r = 0; r < 2; r++) xa[r] = splat2(xs[(bg * 2 + r) * XP + xc]);
#pragma unroll
        for (int p = 0; p < 4; p++) wv[p] = *(const u64*)&ws[i * HS + hg * 2 + 32 * p];
#pragma unroll
        for (int r = 0; r < 2; r++)
#pragma unroll
            for (int p = 0; p < 4; p++) c2[r][p] = fma2(xa[r], wv[p], c2[r][p]);
    }
}

__global__ void __launch_bounds__(NTS, 1) k_sums(const float* __restrict__ inp,
                                                 const float* __restrict__ zz,
                                                 const float* __restrict__ W)
{
    float* smem = (float*)dyn_smem;
    float* ws[2] = { smem, smem + WCNT };
    float* xs[2] = { smem + 2 * WCNT, smem + 2 * WCNT + XCNT };
    const unsigned sbase = (unsigned)__cvta_generic_to_shared(dyn_smem);
    const unsigned ws_a[2] = { sbase, sbase + WCNT * 4u };
    const unsigned xs_a[2] = { sbase + 2u * WCNT * 4u, sbase + (2u * WCNT + XCNT) * 4u };

    const int tid = threadIdx.x;
    const int b0  = (blockIdx.x / NSL) * BT;
    const int h0  = (blockIdx.x % NSL) * HS;
    const int k   = blockIdx.y;
    const int bg  = tid >> 4, hg = tid & 15;   // 2b x 8h per thread (bg 0..63)

    u64 acc[2][4];
#pragma unroll
    for (int r = 0; r < 2; r++)
#pragma unroll
        for (int p = 0; p < 4; p++) acc[r][p] = 0ull;

    stage_wx_async(ws_a[0], xs_a[0], W, inp, zz, k * LC, h0, b0, tid);
    cp_commit(); cp_wait0();
    __syncthreads();

    for (int t = 0; t < LC; t++) {
        const int l = k * LC + t;
        const int cur = t & 1, nxt = cur ^ 1;
        if (t + 1 < LC) {
            stage_wx_async(ws_a[nxt], xs_a[nxt], W, inp, zz, l + 1, h0, b0, tid);
            cp_commit();
        }
        u64 c2[2][4];
        encode_step(c2, ws[cur], xs[cur], bg, hg);
#pragma unroll
        for (int r = 0; r < 2; r++) {
            __half* crow = g_c16 + ((size_t)l * Bsz + b0 + bg * 2 + r) * Hsz + h0;
#pragma unroll
            for (int p = 0; p < 4; p++) {
                acc[r][p] = add2(acc[r][p], c2[r][p]);
                float2 f = *(float2*)&c2[r][p];
                *(__half2*)&crow[hg * 2 + 32 * p] = __floats2half2_rn(f.x, f.y);
            }
        }
        cp_wait0();
        __syncthreads();
    }

    float* sb = g_S + (size_t)k * BH + (size_t)b0 * Hsz + h0;
#pragma unroll
    for (int r = 0; r < 2; r++)
#pragma unroll
        for (int p = 0; p < 4; p++)
            *(u64*)&sb[(size_t)(bg * 2 + r) * Hsz + hg * 2 + 32 * p] = acc[r][p];
}

__global__ void k_scan(const float* __restrict__ benc)
{
    const int idx = blockIdx.x * 256 + threadIdx.x;
    float run = benc[idx & (Hsz - 1)];
#pragma unroll 5
    for (int k = 0; k < NC; k++) {
        g_P[(size_t)k * BH + idx] = run;
        run += g_S[(size_t)k * BH + idx];
    }
}

// ---------------------------------------------------------------------------
// k_all: R10 known-good (untouched). prefix (registers, fed by staged c16)
// + HMMA tf32 decode. Block = (btile*NSL + slice, chunk), 512 threads.
// ---------------------------------------------------------------------------
__global__ void __launch_bounds__(NT) k_all(const float* __restrict__ Vmu,
                                            const float* __restrict__ Vsg,
                                            const float* __restrict__ Vpi)
{
    char* smem = dyn_smem;
    const unsigned sbase = (unsigned)__cvta_generic_to_shared(dyn_smem);
    unsigned* vs_u[2] = { (unsigned*)(smem + SM_VS0), (unsigned*)(smem + SM_VS1) };
    unsigned* hs_u    = (unsigned*)(smem + SM_HS);
    __half*   cs[2]   = { (__half*)(smem + SM_C0), (__half*)(smem + SM_C1) };
    float*    redp    = (float*)(smem + SM_RED);
    const unsigned cs_a[2] = { sbase + SM_C0, sbase + SM_C1 };

    const int tid = threadIdx.x;
    const int wid = tid >> 5, lane = tid & 31;
    const int b0  = (blockIdx.x / NSL) * BT;
    const int s   = blockIdx.x % NSL;
    const int h0  = s * HS;
    const int k   = blockIdx.y;
    const int bg  = tid >> 4, hg = tid & 15;   // acc owner: 4b x 8h
    const int sb  = wid & 7;                   // b strip (16 rows)
    const int kh  = wid >> 3;                  // K half (64 h)
    const int rbase = sb * 16 + (lane >> 2);
    const int kl  = lane & 3;

    unsigned vq[10], bdst[10];
#pragma unroll
    for (int q = 0; q < 10; q++) {
        int u = tid + NT * q;
        int h = u / 40, jc = u % 40;
        unsigned tag, off;
        if (jc < 15)      { tag = 0u; off = (h0 + h) * Osz + jc; }
        else if (jc < 30) { tag = 1u; off = (h0 + h) * Osz + (jc - 15); }
        else if (jc < 35) { tag = 2u; off = (h0 + h) * Msz + (jc - 30); }
        else              { tag = 3u; off = 0; }
        vq[q] = (tag << 30) | off;
        bdst[q] = (unsigned)(h * 40 + jc);
    }

    auto load_V = [&](int l, unsigned vreg[10]) {
        const size_t lmu = (size_t)l * (Hsz * Osz);
        const size_t lpi = (size_t)l * (Hsz * Msz);
#pragma unroll
        for (int q = 0; q < 10; q++) {
            unsigned tag = vq[q] >> 30, off = vq[q] & 0x3FFFFFFFu;
            float v = 0.0f;
            if (tag == 0u)      v = Vmu[lmu + off];
            else if (tag == 1u) v = Vsg[lmu + off];
            else if (tag == 2u) v = Vpi[lpi + off];
            vreg[q] = f2tf32(v);
        }
    };
    auto stage_c = [&](int l, unsigned ca) {
#pragma unroll
        for (int q = 0; q < 4; q++) {
            int idx = tid + NT * q;
            int row = idx >> 4, ch = idx & 15;
            cp16(ca + (unsigned)(row * CP + ch * 8) * 2,
                 g_c16 + ((size_t)l * Bsz + b0 + row) * Hsz + h0 + ch * 8);
        }
        cp_commit();
    };
    auto publish_A = [&](u64 acc[4][4]) {
#pragma unroll
        for (int r = 0; r < 4; r++) {
            const int b = bg * 4 + r;
#pragma unroll
            for (int p = 0; p < 4; p++) {
                float2 v = *(float2*)&acc[r][p];
                unsigned lo = f2tf32(fmaxf(v.x, 0.0f));
                unsigned hi = f2tf32(fmaxf(v.y, 0.0f));
                u64 pk; asm("mov.b64 %0, {%1, %2};" : "=l"(pk) : "r"(lo), "r"(hi));
                *(u64*)&hs_u[b * HP2 + hg * 2 + 32 * p] = pk;
            }
        }
    };

    // prologue
    stage_c(k * LC, cs_a[0]);
    {
        unsigned v0[10];
        load_V(k * LC, v0);
#pragma unroll
        for (int q = 0; q < 10; q++) vs_u[0][bdst[q]] = v0[q];
    }
    u64 acc[4][4];
    {
        const float* P = g_P + (size_t)k * BH + (size_t)b0 * Hsz + h0;
#pragma unroll
        for (int r = 0; r < 4; r++)
#pragma unroll
            for (int p = 0; p < 4; p++) {
                float2 v = *(const float2*)&P[(size_t)(bg * 4 + r) * Hsz + hg * 2 + 32 * p];
                acc[r][p] = *(const u64*)&v;
            }
    }
    publish_A(acc);
    cp_wait0();
    __syncthreads();

    for (int t = 0; t < LC; t++) {
        const int l = k * LC + t;
        const int cur = t & 1, nxt = cur ^ 1;

        unsigned vreg[10];
        if (t + 1 < LC) {
            stage_c(l + 1, cs_a[nxt]);
            load_V(l + 1, vreg);
        }

        float d[5][4];
#pragma unroll
        for (int n = 0; n < 5; n++)
#pragma unroll
            for (int u = 0; u < 4; u++) d[n][u] = 0.0f;

        const unsigned* vcur = vs_u[cur];
#pragma unroll
        for (int kc = 0; kc < 8; kc++) {
            const int k0 = kh * 64 + kc * 8;
            unsigned a0 = hs_u[rbase * HP2 + k0 + kl];
            unsigned a1 = hs_u[(rbase + 8) * HP2 + k0 + kl];
            unsigned a2 = hs_u[rbase * HP2 + k0 + 4 + kl];
            unsigned a3 = hs_u[(rbase + 8) * HP2 + k0 + 4 + kl];
#pragma unroll
            for (int n = 0; n < 5; n++) {
                unsigned bf0 = vcur[(k0 + kl) * 40 + n * 8 + (lane >> 2)];
                unsigned bf1 = vcur[(k0 + 4 + kl) * 40 + n * 8 + (lane >> 2)];
                mma_tf32(d[n], a0, a1, a2, a3, bf0, bf1);
            }
        }

        if (kh) {
#pragma unroll
            for (int n = 0; n < 5; n++) {
                *(float2*)&redp[rbase * 40 + n * 8 + 2 * kl]       = make_float2(d[n][0], d[n][1]);
                *(float2*)&redp[(rbase + 8) * 40 + n * 8 + 2 * kl] = make_float2(d[n][2], d[n][3]);
            }
        }

        {
            const __half* cb = cs[cur];
#pragma unroll
            for (int r = 0; r < 4; r++)
#pragma unroll
                for (int p = 0; p < 4; p++) {
                    __half2 h2 = *(const __half2*)&cb[(bg * 4 + r) * CP + hg * 2 + 32 * p];
                    float2 c = __half22float2(h2);
                    float2 a = *(float2*)&acc[r][p];
                    a.x += c.x; a.y += c.y;
                    acc[r][p] = *(u64*)&a;
                }
        }

        __syncthreads();

        if (!kh) {
            float* dstb = g_part + ((size_t)s * BL + (size_t)l * Bsz + b0) * 40;
#pragma unroll
            for (int n = 0; n < 5; n++) {
                const int j = n * 8 + 2 * kl;
                float2 r0 = *(float2*)&redp[rbase * 40 + j];
                float2 r1 = *(float2*)&redp[(rbase + 8) * 40 + j];
                *(float2*)&dstb[(size_t)rbase * 40 + j] =
                    make_float2(d[n][0] + r0.x, d[n][1] + r0.y);
                *(float2*)&dstb[(size_t)(rbase + 8) * 40 + j] =
                    make_float2(d[n][2] + r1.x, d[n][3] + r1.y);
            }
        }

        publish_A(acc);
        if (t + 1 < LC) {
#pragma unroll
            for (int q = 0; q < 10; q++) vs_u[nxt][bdst[q]] = vreg[q];
            cp_wait0();
        }
        __syncthreads();
    }
}

// ---------------------------------------------------------------------------
// k_reduce: sum slices + output biases. g_part layout [s][l*B + b][40].
// ---------------------------------------------------------------------------
__global__ void __launch_bounds__(280) k_reduce(const float* __restrict__ bmu,
                                                const float* __restrict__ bsg,
                                                const float* __restrict__ bpi,
                                                float* __restrict__ out)
{
    const int p = threadIdx.x / 35;
    const int j = threadIdx.x % 35;
    const size_t pr = (size_t)blockIdx.x * 8 + p;
    const int l = (int)(pr >> 8);
    const int b = (int)(pr & 255);

    float v = 0.0f;
#pragma unroll
    for (int s = 0; s < NSL; s++)
        v += g_part[((size_t)s * BL + pr) * 40 + j];

    float bias;
    if (j < 15)      bias = bmu[l * Osz + j];
    else if (j < 30) bias = bsg[l * Osz + (j - 15)];
    else             bias = bpi[l * Msz + (j - 30)];

    out[((size_t)b * Lsz + l) * Jsz + j] = v + bias;
}

// ---------------------------------------------------------------------------
extern "C" void kernel_launch(void* const* d_in, const int* in_sizes, int n_in,
                              void* d_out, int out_size)
{
    const float* inp  = (const float*)d_in[0];
    const float* zz   = (const float*)d_in[1];
    const float* W    = (const float*)d_in[2];
    const float* benc = (const float*)d_in[3];
    const float* Vmu  = (const float*)d_in[4];
    const float* bmu  = (const float*)d_in[5];
    const float* Vsg  = (const float*)d_in[6];
    const float* bsg  = (const float*)d_in[7];
    const float* Vpi  = (const float*)d_in[8];
    const float* bpi  = (const float*)d_in[9];
    float* out = (float*)d_out;

    const int sm1 = (2 * WCNT + 2 * XCNT) * (int)sizeof(float);   // 80.9 KB
    cudaFuncSetAttribute(k_sums, cudaFuncAttributeMaxDynamicSharedMemorySize, sm1);
    cudaFuncSetAttribute(k_all,  cudaFuncAttributeMaxDynamicSharedMemorySize, SM_TOT);

    k_sums<<<dim3(NBT * NSL, NC), NTS, sm1>>>(inp, zz, W);
    k_scan<<<BH / 256, 256>>>(benc);
    k_all <<<dim3(NBT * NSL, NC), NT, SM_TOT>>>(Vmu, Vsg, Vpi);
    k_reduce<<<BL / 8, 280>>>(bmu, bsg, bpi, out);
}

// round 14
// speedup vs baseline: 1.1983x; 1.1983x over previous
#include <cuda_runtime.h>
#include <cuda_fp16.h>
#include <cstdint>

#define Bsz 256
#define Lsz 500
#define Dsz 3
#define Csz 32
#define Isz 35
#define Hsz 512
#define Msz 5
#define Osz 15
#define Jsz 35
#define NC  50
#define LC  10
#define BH  (Bsz*Hsz)   /* 131072 */
#define BL  (Bsz*Lsz)   /* 128000 */
#define NSL 4           /* h slices */
#define HS  (Hsz/NSL)   /* 128 */
#define BT  128         /* b tile */
#define NBT (Bsz/BT)    /* 2 */
#define XP  44          /* xs row stride (floats), k_sums */
#define NT  512

#define WCNT (Isz*HS)   /* 4480 */
#define XCNT (BT*XP)    /* 5632 */

/* k_all v4 smem: hs[2][128][68] u32 + vs[2][64][40] u32 */
#define HROW 68
#define HBUF (128*HROW)              /* 8704 u32 per buffer */
#define VBUF (64*40)                 /* 2560 u32 per buffer */
#define SM_HS 0
#define SM_VS (2*HBUF*4)             /* 69632 */
#define SMA_TOT (SM_VS + 2*VBUF*4)   /* 90112 B */

extern __shared__ __align__(16) char dyn_smem[];

// Scratch
__device__ __align__(16) float  g_S[(size_t)NC * BH];
__device__ __align__(16) float  g_P[(size_t)NC * BH];
__device__ __align__(16) float  g_part[(size_t)NSL * BL * 40];
__device__ __align__(16) __half g_c16[(size_t)Lsz * BH];

using u64 = unsigned long long;

__device__ __forceinline__ u64 splat2(float x) {
    u64 r; unsigned u = __float_as_uint(x);
    asm("mov.b64 %0, {%1, %1};" : "=l"(r) : "r"(u));
    return r;
}
__device__ __forceinline__ u64 fma2(u64 a, u64 b, u64 c) {
    u64 d; asm("fma.rn.f32x2 %0, %1, %2, %3;" : "=l"(d) : "l"(a), "l"(b), "l"(c));
    return d;
}
__device__ __forceinline__ u64 add2(u64 a, u64 b) {
    u64 d; asm("add.rn.f32x2 %0, %1, %2;" : "=l"(d) : "l"(a), "l"(b));
    return d;
}
__device__ __forceinline__ void cp16(unsigned dst, const void* src) {
    asm volatile("cp.async.ca.shared.global [%0], [%1], 16;" :: "r"(dst), "l"(src));
}
__device__ __forceinline__ void cp4(unsigned dst, const void* src) {
    asm volatile("cp.async.ca.shared.global [%0], [%1], 4;" :: "r"(dst), "l"(src));
}
__device__ __forceinline__ void cp_commit() { asm volatile("cp.async.commit_group;"); }
__device__ __forceinline__ void cp_wait0()  { asm volatile("cp.async.wait_group 0;"); }
__device__ __forceinline__ void barrier0()  { asm volatile("barrier.sync 0;" ::: "memory"); }

// m16n8k16 fp16 HMMA, fp32 accumulate (fragment layout validated in R11)
__device__ __forceinline__ void mma_f16(float d[4],
                                        unsigned a0, unsigned a1, unsigned a2, unsigned a3,
                                        unsigned b0, unsigned b1) {
    asm volatile(
        "mma.sync.aligned.m16n8k16.row.col.f32.f16.f16.f32 "
        "{%0,%1,%2,%3}, {%4,%5,%6,%7}, {%8,%9}, {%0,%1,%2,%3};"
        : "+f"(d[0]), "+f"(d[1]), "+f"(d[2]), "+f"(d[3])
        : "r"(a0), "r"(a1), "r"(a2), "r"(a3), "r"(b0), "r"(b1));
}

// ---------------------------------------------------------------------------
// k_sums: EXACT R10 known-good (153us). fp32 chunk sums + fp16 c store.
// ---------------------------------------------------------------------------
__device__ __forceinline__ void stage_wx_async(unsigned ws_a, unsigned xs_a,
                                               const float* __restrict__ W,
                                               const float* __restrict__ inp,
                                               const float* __restrict__ zz,
                                               int l, int h0, int b0, int tid)
{
    const float4* wsrc = (const float4*)(W + (size_t)l * (Isz * Hsz)) + (h0 >> 2);
#pragma unroll
    for (int q = 0; q < 3; q++) {
        int idx = tid + NT * q;
        if (idx < Isz * 32) {
            int row = idx >> 5, col = idx & 31;
            cp16(ws_a + (unsigned)(row * 32 + col) * 16, wsrc + row * 128 + col);
        }
    }
#pragma unroll
    for (int q = 0; q < 2; q++) {
        int idx = tid + NT * q;
        int b = idx >> 3, qf = idx & 7;
        cp16(xs_a + (unsigned)(b * XP + 4 + qf * 4) * 4,
             zz + (size_t)(b0 + b) * (Lsz * Csz) + (size_t)l * Csz + qf * 4);
    }
    if (tid < BT * Dsz) {
        int b = tid / Dsz, i = tid % Dsz;
        cp4(xs_a + (unsigned)(b * XP + i) * 4,
            inp + (size_t)(b0 + b) * (Lsz * Dsz) + (size_t)l * Dsz + i);
    }
}

__device__ __forceinline__ void encode_step(u64 c2[4][4], const float* ws,
                                            const float* xs, int bg, int hg)
{
#pragma unroll
    for (int r = 0; r < 4; r++)
#pragma unroll
        for (int p = 0; p < 4; p++) c2[r][p] = 0ull;
#pragma unroll
    for (int i = 0; i < Isz; i++) {
        const int xc = (i < Dsz) ? i : i + 1;
        u64 xa[4], wv[4];
#pragma unroll
        for (int r = 0; r < 4; r++) xa[r] = splat2(xs[(bg * 4 + r) * XP + xc]);
#pragma unroll
        for (int p = 0; p < 4; p++) wv[p] = *(const u64*)&ws[i * HS + hg * 2 + 32 * p];
#pragma unroll
        for (int r = 0; r < 4; r++)
#pragma unroll
            for (int p = 0; p < 4; p++) c2[r][p] = fma2(xa[r], wv[p], c2[r][p]);
    }
}

__global__ void __launch_bounds__(NT) k_sums(const float* __restrict__ inp,
                                             const float* __restrict__ zz,
                                             const float* __restrict__ W)
{
    float* smem = (float*)dyn_smem;
    float* ws[2] = { smem, smem + WCNT };
    float* xs[2] = { smem + 2 * WCNT, smem + 2 * WCNT + XCNT };
    const unsigned sbase = (unsigned)__cvta_generic_to_shared(dyn_smem);
    const unsigned ws_a[2] = { sbase, sbase + WCNT * 4u };
    const unsigned xs_a[2] = { sbase + 2u * WCNT * 4u, sbase + (2u * WCNT + XCNT) * 4u };

    const int tid = threadIdx.x;
    const int b0  = (blockIdx.x / NSL) * BT;
    const int h0  = (blockIdx.x % NSL) * HS;
    const int k   = blockIdx.y;
    const int bg  = tid >> 4, hg = tid & 15;

    u64 acc[4][4];
#pragma unroll
    for (int r = 0; r < 4; r++)
#pragma unroll
        for (int p = 0; p < 4; p++) acc[r][p] = 0ull;

    stage_wx_async(ws_a[0], xs_a[0], W, inp, zz, k * LC, h0, b0, tid);
    cp_commit(); cp_wait0();
    __syncthreads();

    for (int t = 0; t < LC; t++) {
        const int l = k * LC + t;
        const int cur = t & 1, nxt = cur ^ 1;
        if (t + 1 < LC) {
            stage_wx_async(ws_a[nxt], xs_a[nxt], W, inp, zz, l + 1, h0, b0, tid);
            cp_commit();
        }
        u64 c2[4][4];
        encode_step(c2, ws[cur], xs[cur], bg, hg);
#pragma unroll
        for (int r = 0; r < 4; r++) {
            __half* crow = g_c16 + ((size_t)l * Bsz + b0 + bg * 4 + r) * Hsz + h0;
#pragma unroll
            for (int p = 0; p < 4; p++) {
                acc[r][p] = add2(acc[r][p], c2[r][p]);
                float2 f = *(float2*)&c2[r][p];
                *(__half2*)&crow[hg * 2 + 32 * p] = __floats2half2_rn(f.x, f.y);
            }
        }
        cp_wait0();
        __syncthreads();
    }

    float* sb = g_S + (size_t)k * BH + (size_t)b0 * Hsz + h0;
#pragma unroll
    for (int r = 0; r < 4; r++)
#pragma unroll
        for (int p = 0; p < 4; p++)
            *(u64*)&sb[(size_t)(bg * 4 + r) * Hsz + hg * 2 + 32 * p] = acc[r][p];
}

__global__ void k_scan(const float* __restrict__ benc)
{
    const int idx = blockIdx.x * 256 + threadIdx.x;
    float run = benc[idx & (Hsz - 1)];
#pragma unroll 5
    for (int k = 0; k < NC; k++) {
        g_P[(size_t)k * BH + idx] = run;
        run += g_S[(size_t)k * BH + idx];
    }
}

// ---------------------------------------------------------------------------
// k_all v4: warp-specialized. 512 threads.
//   warps 0-7 (mma):   sb = wid -> 16-row b strip, FULL 128-h K per warp,
//                      fp16 m16n8k16 from hs[cur]/vs[cur]; store g_part;
//                      prefetch V[l+1] -> vs[nxt].
//   warps 8-15 (state): thread owns 1b x 64h of acc (fp32 regs); acc += c16[l]
//                      (direct LDG, 1-step prefetch); publish relu -> hs[nxt].
// ONE barrier per step. hs/vs double-buffered.
// ---------------------------------------------------------------------------
__global__ void __launch_bounds__(NT) k_all(const float* __restrict__ Vmu,
                                            const float* __restrict__ Vsg,
                                            const float* __restrict__ Vpi)
{
    unsigned* hsb = (unsigned*)(dyn_smem + SM_HS);   // [2][128][HROW]
    unsigned* vsb = (unsigned*)(dyn_smem + SM_VS);   // [2][64][40]

    const int tid = threadIdx.x;
    const int wid = tid >> 5, lane = tid & 31;
    const int b0  = (blockIdx.x / NSL) * BT;
    const int s   = blockIdx.x % NSL;
    const int h0  = s * HS;
    const int l0  = blockIdx.y * LC;

    if (wid < 8) {
        // ================= MMA role =================
        const int sb = wid;
        const int rq = lane >> 2, kl = lane & 3;
        const int rb = sb * 16 + rq;

        // V staging descriptors: u = tid + 256q -> h2 = u/40 (0..63), jc = u%40
        unsigned vq[10], vdst[10];
#pragma unroll
        for (int q = 0; q < 10; q++) {
            int u = tid + 256 * q;
            int h2 = u / 40, jc = u % 40;
            unsigned tag, off;
            if (jc < 15)      { tag = 0u; off = (h0 + 2 * h2) * Osz + jc; }
            else if (jc < 30) { tag = 1u; off = (h0 + 2 * h2) * Osz + (jc - 15); }
            else if (jc < 35) { tag = 2u; off = (h0 + 2 * h2) * Msz + (jc - 30); }
            else              { tag = 3u; off = 0; }
            vq[q] = (tag << 30) | off;
            vdst[q] = (unsigned)(h2 * 40 + jc);
        }
        auto load_V = [&](int l, unsigned vreg[10]) {
            const size_t lmu = (size_t)l * (Hsz * Osz);
            const size_t lpi = (size_t)l * (Hsz * Msz);
#pragma unroll
            for (int q = 0; q < 10; q++) {
                unsigned tag = vq[q] >> 30, off = vq[q] & 0x3FFFFFFFu;
                float v0 = 0.0f, v1 = 0.0f;
                if (tag == 0u)      { v0 = Vmu[lmu + off]; v1 = Vmu[lmu + off + Osz]; }
                else if (tag == 1u) { v0 = Vsg[lmu + off]; v1 = Vsg[lmu + off + Osz]; }
                else if (tag == 2u) { v0 = Vpi[lpi + off]; v1 = Vpi[lpi + off + Msz]; }
                __half2 h2v = __floats2half2_rn(v0, v1);
                vreg[q] = *(unsigned*)&h2v;
            }
        };

        // prologue: stage V[l0] into vs[0]
        {
            unsigned v0[10];
            load_V(l0, v0);
#pragma unroll
            for (int q = 0; q < 10; q++) vsb[vdst[q]] = v0[q];
        }
        barrier0();

        for (int t = 0; t < LC; t++) {
            const int l = l0 + t;
            const int cur = t & 1, nxt = cur ^ 1;
            const unsigned* hsc = hsb + cur * HBUF;
            const unsigned* vsc = vsb + cur * VBUF;

            unsigned vreg[10];
            if (t + 1 < LC) load_V(l + 1, vreg);

            float d[5][4];
#pragma unroll
            for (int n = 0; n < 5; n++)
#pragma unroll
                for (int u = 0; u < 4; u++) d[n][u] = 0.0f;

#pragma unroll
            for (int kc = 0; kc < 8; kc++) {
                const int k0h = kc * 8;     // half2 index base (16 h per kc)
                unsigned a0 = hsc[rb * HROW + k0h + kl];
                unsigned a1 = hsc[(rb + 8) * HROW + k0h + kl];
                unsigned a2 = hsc[rb * HROW + k0h + 4 + kl];
                unsigned a3 = hsc[(rb + 8) * HROW + k0h + 4 + kl];
#pragma unroll
                for (int n = 0; n < 5; n++) {
                    unsigned bf0 = vsc[(k0h + kl) * 40 + n * 8 + rq];
                    unsigned bf1 = vsc[(k0h + 4 + kl) * 40 + n * 8 + rq];
                    mma_f16(d[n], a0, a1, a2, a3, bf0, bf1);
                }
            }

            // store partials (full-K, no cross-warp reduce needed)
            {
                float* d0 = g_part + ((size_t)s * BL + (size_t)l * Bsz + (b0 + rb)) * 40;
                float* d1 = g_part + ((size_t)s * BL + (size_t)l * Bsz + (b0 + rb + 8)) * 40;
#pragma unroll
                for (int n = 0; n < 5; n++) {
                    const int j = n * 8 + 2 * kl;
                    *(float2*)&d0[j] = make_float2(d[n][0], d[n][1]);
                    *(float2*)&d1[j] = make_float2(d[n][2], d[n][3]);
                }
            }

            if (t + 1 < LC) {
                unsigned* vsn = vsb + nxt * VBUF;
#pragma unroll
                for (int q = 0; q < 10; q++) vsn[vdst[q]] = vreg[q];
            }
            barrier0();
        }
    } else {
        // ================= STATE role =================
        const int stid = tid - 256;           // 0..255
        const int b    = stid >> 1;           // 0..127
        const int shf  = stid & 1;            // h half: h = shf*64 + 2*j2
        const unsigned hcol = (unsigned)(b * HROW + shf * 32);

        // acc: 32 float2 (64 fp32)
        u64 acc[32];
        {
            const float* P = g_P + (size_t)blockIdx.y * BH
                           + (size_t)(b0 + b) * Hsz + h0 + shf * 64;
#pragma unroll
            for (int j2 = 0; j2 < 32; j2++) {
                float2 v = *(const float2*)&P[2 * j2];
                acc[j2] = *(const u64*)&v;
            }
        }
        // publish relu(a[l0]) -> hs[0]
        {
            unsigned* hsn = hsb;
#pragma unroll
            for (int j2 = 0; j2 < 32; j2++) {
                float2 v = *(float2*)&acc[j2];
                __half2 h2v = __floats2half2_rn(fmaxf(v.x, 0.0f), fmaxf(v.y, 0.0f));
                hsn[hcol + j2] = *(unsigned*)&h2v;
            }
        }
        // preload c16[l0]
        const __half* crow_base = g_c16 + ((size_t)(b0 + b)) * Hsz + h0 + shf * 64;
        uint4 c4[8];
        {
            const uint4* src = (const uint4*)(g_c16
                + ((size_t)l0 * Bsz + b0 + b) * Hsz + h0 + shf * 64);
#pragma unroll
            for (int q = 0; q < 8; q++) c4[q] = src[q];
        }
        barrier0();

        for (int t = 0; t < LC; t++) {
            const int cur = t & 1, nxt = cur ^ 1;

            // acc += c16[l] (consume c4), then reload c4 <- c16[l+1]
#pragma unroll
            for (int q = 0; q < 8; q++) {
                unsigned w[4] = { c4[q].x, c4[q].y, c4[q].z, c4[q].w };
#pragma unroll
                for (int wq = 0; wq < 4; wq++) {
                    float2 c = __half22float2(*(__half2*)&w[wq]);
                    float2 a = *(float2*)&acc[q * 4 + wq];
                    a.x += c.x; a.y += c.y;
                    acc[q * 4 + wq] = *(u64*)&a;
                }
                if (t + 1 < LC) {
                    const uint4* src = (const uint4*)(g_c16
                        + ((size_t)(l0 + t + 1) * Bsz + b0 + b) * Hsz + h0 + shf * 64);
                    c4[q] = src[q];
                }
            }
            (void)crow_base;

            // publish relu(a[l+1]) -> hs[nxt]
            if (t + 1 < LC) {
                unsigned* hsn = hsb + nxt * HBUF;
#pragma unroll
                for (int j2 = 0; j2 < 32; j2++) {
                    float2 v = *(float2*)&acc[j2];
                    __half2 h2v = __floats2half2_rn(fmaxf(v.x, 0.0f), fmaxf(v.y, 0.0f));
                    hsn[hcol + j2] = *(unsigned*)&h2v;
                }
            }
            barrier0();
        }
    }
}

// ---------------------------------------------------------------------------
// k_reduce: sum slices + output biases. g_part layout [s][l*B + b][40].
// ---------------------------------------------------------------------------
__global__ void __launch_bounds__(280) k_reduce(const float* __restrict__ bmu,
                                                const float* __restrict__ bsg,
                                                const float* __restrict__ bpi,
                                                float* __restrict__ out)
{
    const int p = threadIdx.x / 35;
    const int j = threadIdx.x % 35;
    const size_t pr = (size_t)blockIdx.x * 8 + p;
    const int l = (int)(pr >> 8);
    const int b = (int)(pr & 255);

    float v = 0.0f;
#pragma unroll
    for (int s = 0; s < NSL; s++)
        v += g_part[((size_t)s * BL + pr) * 40 + j];

    float bias;
    if (j < 15)      bias = bmu[l * Osz + j];
    else if (j < 30) bias = bsg[l * Osz + (j - 15)];
    else             bias = bpi[l * Msz + (j - 30)];

    out[((size_t)b * Lsz + l) * Jsz + j] = v + bias;
}

// ---------------------------------------------------------------------------
extern "C" void kernel_launch(void* const* d_in, const int* in_sizes, int n_in,
                              void* d_out, int out_size)
{
    const float* inp  = (const float*)d_in[0];
    const float* zz   = (const float*)d_in[1];
    const float* W    = (const float*)d_in[2];
    const float* benc = (const float*)d_in[3];
    const float* Vmu  = (const float*)d_in[4];
    const float* bmu  = (const float*)d_in[5];
    const float* Vsg  = (const float*)d_in[6];
    const float* bsg  = (const float*)d_in[7];
    const float* Vpi  = (const float*)d_in[8];
    const float* bpi  = (const float*)d_in[9];
    float* out = (float*)d_out;

    const int sm1 = (2 * WCNT + 2 * XCNT) * (int)sizeof(float);   // 80.9 KB
    cudaFuncSetAttribute(k_sums, cudaFuncAttributeMaxDynamicSharedMemorySize, sm1);
    cudaFuncSetAttribute(k_all,  cudaFuncAttributeMaxDynamicSharedMemorySize, SMA_TOT);

    k_sums<<<dim3(NBT * NSL, NC), NT, sm1>>>(inp, zz, W);
    k_scan<<<BH / 256, 256>>>(benc);
    k_all <<<dim3(NBT * NSL, NC), NT, SMA_TOT>>>(Vmu, Vsg, Vpi);
    k_reduce<<<BL / 8, 280>>>(bmu, bsg, bpi, out);
}